// round 2
// baseline (speedup 1.0000x reference)
#include <cuda_runtime.h>
#include <math_constants.h>

// GATv2 additive attention scores + masked softmax.
// shapes: q (2,8,384,64) f32, k (2,8,384,64) f32, attention (1,8,1,1,64) f32,
//         mask (2,8,384,384) int32 (0/1), out (2,8,384,384) f32
//
// score(b,h,i,j) = sum_d a[h,d] * silu(q[b,h,i,d] + k[b,h,j,d])
// w = softmax_j(where(mask, -inf, score));  w = where(mask, 0, w)

#define B_   2
#define H_   8
#define LQ_  384
#define LK_  384
#define D_   64
#define ROWS 8          // q rows per block (1 warp per row)
#define PAD  68         // smem row stride in floats (conflict-free LDS.128)
#define NC   12         // LK / 32 j-chunks per lane

__global__ __launch_bounds__(256, 2)
void gatv2_kernel(const float* __restrict__ q, const float* __restrict__ k,
                  const float* __restrict__ att, const int* __restrict__ mask,
                  float* __restrict__ out)
{
    extern __shared__ float smem[];
    float* ks = smem;                    // [LK][PAD]
    float* qs = ks + LK_ * PAD;          // [ROWS][PAD]
    float* as = qs + ROWS * PAD;         // [D]

    const int ntiles = LQ_ / ROWS;       // 48
    int blk   = blockIdx.x;
    int bh    = blk / ntiles;            // b*H + h
    int itile = blk - bh * ntiles;
    int h     = bh & (H_ - 1);

    int tid = threadIdx.x;

    // ---- stage K(b,h) tile: 384x64 f32, float4 coalesced loads ----
    const float4* kg = (const float4*)(k + (size_t)bh * LK_ * D_);
    for (int idx = tid; idx < LK_ * D_ / 4; idx += 256) {
        int j = idx >> 4, d4 = idx & 15;
        *(float4*)(ks + j * PAD + d4 * 4) = kg[idx];
    }
    // ---- stage 8 q rows ----
    const float4* qg = (const float4*)(q + ((size_t)bh * LQ_ + itile * ROWS) * D_);
    for (int idx = tid; idx < ROWS * D_ / 4; idx += 256) {
        int i = idx >> 4, d4 = idx & 15;
        *(float4*)(qs + i * PAD + d4 * 4) = qg[idx];
    }
    // ---- stage attention vector for this head ----
    if (tid < D_) as[tid] = att[h * D_ + tid];
    __syncthreads();

    int warp = tid >> 5, lane = tid & 31;
    int i = itile * ROWS + warp;         // global q row
    const float* qrow = qs + warp * PAD;

    float acc[NC];
#pragma unroll
    for (int c = 0; c < NC; c++) acc[c] = 0.f;

    // ---- score accumulation: d4 outer (amortize broadcasts), 12 j-chunks inner ----
    for (int d4 = 0; d4 < D_ / 4; ++d4) {
        float4 q4 = *(const float4*)(qrow + d4 * 4);   // broadcast
        float4 a4 = *(const float4*)(as + d4 * 4);     // broadcast
#pragma unroll
        for (int c = 0; c < NC; c++) {
            float4 k4 = *(const float4*)(ks + (c * 32 + lane) * PAD + d4 * 4);
            float s, e;
            s = q4.x + k4.x; e = __expf(-s); acc[c] += a4.x * __fdividef(s, 1.f + e);
            s = q4.y + k4.y; e = __expf(-s); acc[c] += a4.y * __fdividef(s, 1.f + e);
            s = q4.z + k4.z; e = __expf(-s); acc[c] += a4.z * __fdividef(s, 1.f + e);
            s = q4.w + k4.w; e = __expf(-s); acc[c] += a4.w * __fdividef(s, 1.f + e);
        }
    }

    // ---- mask (int32 0/1) + single-warp softmax over LK=384 ----
    const int* mrow = mask + ((size_t)bh * LQ_ + i) * LK_;
    unsigned mbits = 0;
    float mx = -CUDART_INF_F;
#pragma unroll
    for (int c = 0; c < NC; c++) {
        if (mrow[c * 32 + lane] != 0) { mbits |= (1u << c); acc[c] = -CUDART_INF_F; }
        mx = fmaxf(mx, acc[c]);
    }
#pragma unroll
    for (int o = 16; o; o >>= 1) mx = fmaxf(mx, __shfl_xor_sync(0xffffffffu, mx, o));

    float sum = 0.f;
#pragma unroll
    for (int c = 0; c < NC; c++) {
        float e = ((mbits >> c) & 1u) ? 0.f : __expf(acc[c] - mx);
        acc[c] = e;
        sum += e;
    }
#pragma unroll
    for (int o = 16; o; o >>= 1) sum += __shfl_xor_sync(0xffffffffu, sum, o);

    float inv = (sum > 0.f) ? __fdividef(1.f, sum) : 0.f;  // all-masked row -> zeros

    float* orow = out + ((size_t)bh * LQ_ + i) * LK_;
#pragma unroll
    for (int c = 0; c < NC; c++) orow[c * 32 + lane] = acc[c] * inv;
}

extern "C" void kernel_launch(void* const* d_in, const int* in_sizes, int n_in,
                              void* d_out, int out_size)
{
    const float* q   = (const float*)d_in[0];
    const float* k   = (const float*)d_in[1];
    const float* att = (const float*)d_in[2];
    const int*   m   = (const int*)d_in[3];
    float* out       = (float*)d_out;

    const int smem_bytes = (LK_ * PAD + ROWS * PAD + D_) * (int)sizeof(float); // 106880
    cudaFuncSetAttribute(gatv2_kernel, cudaFuncAttributeMaxDynamicSharedMemorySize, smem_bytes);

    dim3 grid(B_ * H_ * (LQ_ / ROWS));   // 768
    gatv2_kernel<<<grid, 256, smem_bytes>>>(q, k, att, m, out);
}

// round 3
// speedup vs baseline: 1.7600x; 1.7600x over previous
#include <cuda_runtime.h>
#include <math_constants.h>

// GATv2 additive attention scores + masked softmax.
// shapes: q (2,8,384,64) f32, k (2,8,384,64) f32, attention (1,8,1,1,64) f32,
//         mask (2,8,384,384) int32 (0/1), out (2,8,384,384) f32
//
// score(b,h,i,j) = sum_d a[h,d] * silu(q[b,h,i,d] + k[b,h,j,d])
// silu(s) = s*sigmoid(s) = u*(1+tanh(u)), u = s/2  -> MUFU.TANH + FFMA
// q,k are pre-scaled by 0.5 at smem staging so u = qh + kh.
// w = softmax_j(where(mask, -inf, score));  w = where(mask, 0, w)

#define B_   2
#define H_   8
#define LQ_  384
#define LK_  384
#define D_   64
#define ROWS 8          // q rows per block (1 warp per row)
#define PAD  68         // smem row stride in floats (conflict-free LDS.128)
#define NC   12         // LK / 32 j-chunks per lane

__device__ __forceinline__ float tanh_approx(float x) {
    float r;
    asm("tanh.approx.f32 %0, %1;" : "=f"(r) : "f"(x));
    return r;
}

__global__ __launch_bounds__(256, 2)
void gatv2_kernel(const float* __restrict__ q, const float* __restrict__ k,
                  const float* __restrict__ att, const int* __restrict__ mask,
                  float* __restrict__ out)
{
    extern __shared__ float smem[];
    float* ks = smem;                    // [LK][PAD]   (0.5*k)
    float* qs = ks + LK_ * PAD;          // [ROWS][PAD] (0.5*q)
    float* as = qs + ROWS * PAD;         // [D]

    const int ntiles = LQ_ / ROWS;       // 48
    int blk   = blockIdx.x;
    int bh    = blk / ntiles;            // b*H + h
    int itile = blk - bh * ntiles;
    int h     = bh & (H_ - 1);

    int tid = threadIdx.x;

    // ---- stage K(b,h) tile scaled by 0.5: 384x64 f32 ----
    const float4* kg = (const float4*)(k + (size_t)bh * LK_ * D_);
    for (int idx = tid; idx < LK_ * D_ / 4; idx += 256) {
        int j = idx >> 4, d4 = idx & 15;
        float4 v = kg[idx];
        v.x *= 0.5f; v.y *= 0.5f; v.z *= 0.5f; v.w *= 0.5f;
        *(float4*)(ks + j * PAD + d4 * 4) = v;
    }
    // ---- stage 8 q rows scaled by 0.5 ----
    const float4* qg = (const float4*)(q + ((size_t)bh * LQ_ + itile * ROWS) * D_);
    for (int idx = tid; idx < ROWS * D_ / 4; idx += 256) {
        int i = idx >> 4, d4 = idx & 15;
        float4 v = qg[idx];
        v.x *= 0.5f; v.y *= 0.5f; v.z *= 0.5f; v.w *= 0.5f;
        *(float4*)(qs + i * PAD + d4 * 4) = v;
    }
    // ---- stage attention vector for this head ----
    if (tid < D_) as[tid] = att[h * D_ + tid];
    __syncthreads();

    int warp = tid >> 5, lane = tid & 31;
    int i = itile * ROWS + warp;         // global q row
    const float* qrow = qs + warp * PAD;

    float acc[NC];
#pragma unroll
    for (int c = 0; c < NC; c++) acc[c] = 0.f;

    // ---- score accumulation: d4 outer (amortize broadcasts), 12 j-chunks inner ----
    for (int d4 = 0; d4 < D_ / 4; ++d4) {
        float4 q4 = *(const float4*)(qrow + d4 * 4);   // broadcast (0.5*q)
        float4 a4 = *(const float4*)(as + d4 * 4);     // broadcast
#pragma unroll
        for (int c = 0; c < NC; c++) {
            float4 k4 = *(const float4*)(ks + (c * 32 + lane) * PAD + d4 * 4);
            float u, t;
            u = q4.x + k4.x; t = tanh_approx(u); acc[c] = fmaf(a4.x, fmaf(u, t, u), acc[c]);
            u = q4.y + k4.y; t = tanh_approx(u); acc[c] = fmaf(a4.y, fmaf(u, t, u), acc[c]);
            u = q4.z + k4.z; t = tanh_approx(u); acc[c] = fmaf(a4.z, fmaf(u, t, u), acc[c]);
            u = q4.w + k4.w; t = tanh_approx(u); acc[c] = fmaf(a4.w, fmaf(u, t, u), acc[c]);
        }
    }

    // ---- mask (int32 0/1) + single-warp softmax over LK=384 ----
    const int* mrow = mask + ((size_t)bh * LQ_ + i) * LK_;
    unsigned mbits = 0;
    float mx = -CUDART_INF_F;
#pragma unroll
    for (int c = 0; c < NC; c++) {
        if (mrow[c * 32 + lane] != 0) { mbits |= (1u << c); acc[c] = -CUDART_INF_F; }
        mx = fmaxf(mx, acc[c]);
    }
#pragma unroll
    for (int o = 16; o; o >>= 1) mx = fmaxf(mx, __shfl_xor_sync(0xffffffffu, mx, o));

    float sum = 0.f;
#pragma unroll
    for (int c = 0; c < NC; c++) {
        float e = ((mbits >> c) & 1u) ? 0.f : __expf(acc[c] - mx);
        acc[c] = e;
        sum += e;
    }
#pragma unroll
    for (int o = 16; o; o >>= 1) sum += __shfl_xor_sync(0xffffffffu, sum, o);

    float inv = (sum > 0.f) ? __fdividef(1.f, sum) : 0.f;  // all-masked row -> zeros

    float* orow = out + ((size_t)bh * LQ_ + i) * LK_;
#pragma unroll
    for (int c = 0; c < NC; c++) orow[c * 32 + lane] = acc[c] * inv;
}

extern "C" void kernel_launch(void* const* d_in, const int* in_sizes, int n_in,
                              void* d_out, int out_size)
{
    const float* q   = (const float*)d_in[0];
    const float* k   = (const float*)d_in[1];
    const float* att = (const float*)d_in[2];
    const int*   m   = (const int*)d_in[3];
    float* out       = (float*)d_out;

    const int smem_bytes = (LK_ * PAD + ROWS * PAD + D_) * (int)sizeof(float); // 106880
    cudaFuncSetAttribute(gatv2_kernel, cudaFuncAttributeMaxDynamicSharedMemorySize, smem_bytes);

    dim3 grid(B_ * H_ * (LQ_ / ROWS));   // 768
    gatv2_kernel<<<grid, 256, smem_bytes>>>(q, k, att, m, out);
}